// round 15
// baseline (speedup 1.0000x reference)
#include <cuda_runtime.h>
#include <cuda_fp16.h>
#include <math.h>
#include <stdint.h>

#define S_LEN 2048
#define DMODEL 1024
#define NHEADS 16
#define DHEAD 64
#define WIN 256
#define BATCH 2
#define BH (BATCH * NHEADS)
#define MROWS (BATCH * S_LEN)
#define KD 1024
#define ATT_SCALE 0.125f

// ---- mma.sync / ldmatrix / cp.async helpers (baseline PTX) ----
__device__ __forceinline__ uint32_t smem_u32(const void* p) {
    uint32_t a;
    asm("{ .reg .u64 t; cvta.to.shared.u64 t, %1; cvt.u32.u64 %0, t; }" : "=r"(a) : "l"(p));
    return a;
}
__device__ __forceinline__ void ldsm4(uint32_t* r, uint32_t addr) {
    asm volatile("ldmatrix.sync.aligned.m8n8.x4.shared.b16 {%0,%1,%2,%3}, [%4];"
                 : "=r"(r[0]), "=r"(r[1]), "=r"(r[2]), "=r"(r[3]) : "r"(addr));
}
__device__ __forceinline__ void mma16816(float* d, const uint32_t* a, const uint32_t* b) {
    asm volatile("mma.sync.aligned.m16n8k16.row.col.f32.f16.f16.f32 "
        "{%0,%1,%2,%3}, {%4,%5,%6,%7}, {%8,%9}, {%0,%1,%2,%3};"
        : "+f"(d[0]), "+f"(d[1]), "+f"(d[2]), "+f"(d[3])
        : "r"(a[0]), "r"(a[1]), "r"(a[2]), "r"(a[3]), "r"(b[0]), "r"(b[1]));
}
__device__ __forceinline__ void cpa16(uint32_t dst, const void* src) {
    asm volatile("cp.async.cg.shared.global [%0], [%1], 16;" :: "r"(dst), "l"(src));
}
#define CP_COMMIT() asm volatile("cp.async.commit_group;" ::: "memory")
#define CP_WAIT0()  asm volatile("cp.async.wait_group 0;" ::: "memory")
#define CP_WAIT1()  asm volatile("cp.async.wait_group 1;" ::: "memory")

// Scratch (allocation-free rule: __device__ globals)
__device__ __half g_xh[(size_t)MROWS * KD];           // fp16 x
__device__ __half g_ch[(size_t)MROWS * KD];           // fp16 attention out
__device__ __half g_wqh[(size_t)(3 * DMODEL) * KD];   // W_qkv^T fp16 [3072][1024]
__device__ __half g_woh[(size_t)DMODEL * KD];         // W_out^T fp16 [1024][1024]
__device__ __half g_qh[(size_t)BH * S_LEN * DHEAD];   // Q hi  [bh][s][d]
__device__ __half g_ql[(size_t)BH * S_LEN * DHEAD];   // Q lo
__device__ __half g_kh[(size_t)BH * S_LEN * DHEAD];   // K hi
__device__ __half g_kl[(size_t)BH * S_LEN * DHEAD];   // K lo
__device__ __half g_vth[(size_t)BH * DHEAD * S_LEN];  // V^T hi [bh][d][s]

__device__ __forceinline__ void h_split(float v, __half& hi, __half& lo) {
    hi = __float2half_rn(v);
    lo = __float2half_rn(v - __half2float(hi));
}

// ---------------------------------------------------------------------------
// Convert x [4096][1024] f32 -> g_xh fp16
// ---------------------------------------------------------------------------
__global__ __launch_bounds__(256) void conv_x_kernel(const float* __restrict__ src)
{
    int idx = blockIdx.x * 256 + threadIdx.x;
    int m = idx >> 8;
    int c = (idx & 255) << 2;
    float4 v = *(const float4*)(src + (size_t)m * KD + c);
    size_t o = (size_t)m * KD + c;
    *(__half2*)(g_xh + o)     = __half2{__float2half_rn(v.x), __float2half_rn(v.y)};
    *(__half2*)(g_xh + o + 2) = __half2{__float2half_rn(v.z), __float2half_rn(v.w)};
}

// ---------------------------------------------------------------------------
// Transpose + fp16 convert BOTH weights in one launch.
// blocks [0,96): Wqkv (NC=3072) -> g_wqh; blocks [96,128): Wout -> g_woh.
// ---------------------------------------------------------------------------
__global__ __launch_bounds__(256) void wconv_all_kernel(
    const float* __restrict__ Wq, const float* __restrict__ Wo)
{
    __shared__ float tile[32][33];
    const int bx = blockIdx.x;
    const float* src; __half* dst; int NC, n0;
    if (bx < 96) { src = Wq; dst = g_wqh; NC = 3072; n0 = bx * 32; }
    else         { src = Wo; dst = g_woh; NC = 1024; n0 = (bx - 96) * 32; }
    int k0 = blockIdx.y * 32;
    int tx = threadIdx.x, ty = threadIdx.y;   // 32 x 8
#pragma unroll
    for (int i = 0; i < 32; i += 8)
        tile[ty + i][tx] = src[(size_t)(k0 + ty + i) * NC + n0 + tx];
    __syncthreads();
#pragma unroll
    for (int i = 0; i < 32; i += 8) {
        float v = tile[tx][ty + i];
        int n = n0 + ty + i, k = k0 + tx;
        dst[(size_t)n * KD + k] = __float2half_rn(v);
    }
}

// ---------------------------------------------------------------------------
// fp16 mma.sync GEMM: 256 thr, 8 warps (4Mx2N, 32x64 warp tiles), BK=64
// (two k32 sub-chunks per stage), 3x32KB stages, ONE barrier pair per 64 K.
// MODE 0: A=g_xh B=g_wqh; epilogue Q/K hi+lo, V^T scalar scatter (R12-best).
// MODE 1: A=g_ch B=g_woh -> fp32 out.
// ---------------------------------------------------------------------------
#define BM 128
#define BN 128
#define NIT2 16                 // 1024 / 64
#define SB_OFF 8192             // B within a 16KB sub-chunk
#define SUB_BYTES 16384         // one k32 sub-chunk (A 8K + B 8K)
#define STG2_BYTES 32768        // BK=64 stage
#define SMEM_DYN (3 * STG2_BYTES)   // 98304

template <int MODE>
__global__ __launch_bounds__(256, 2) void mma_gemm_kernel(
    const float* __restrict__ bias, float* __restrict__ out)
{
    extern __shared__ char dsm[];
    const __half* __restrict__ Ah = MODE ? g_ch : g_xh;
    const __half* __restrict__ Bh = MODE ? g_woh : g_wqh;

    const int tid = threadIdx.x;
    const int wid = tid >> 5, lid = tid & 31;
    const int m0 = blockIdx.y * BM, n0 = blockIdx.x * BN;
    const int wm = wid & 3, wn = wid >> 2;       // 4x2 warp grid, 32x64 tiles
    const uint32_t sbase = smem_u32(dsm);

    const int row = tid >> 1;
    const int c0  = (tid & 1) << 1;
    const int sw  = (row >> 1) & 3;
    const __half* gA = Ah + (size_t)(m0 + row) * KD;
    const __half* gB = Bh + (size_t)(n0 + row) * KD;
    uint32_t dA[2], dB[2];
#pragma unroll
    for (int j = 0; j < 2; j++) {
        dA[j] = sbase + (uint32_t)(row * 64 + (((c0 + j) ^ sw) << 4));
        dB[j] = dA[j] + SB_OFF;
    }

    uint32_t aAd[2], bAd[4];
#pragma unroll
    for (int mi = 0; mi < 2; mi++) {
        int r = wm * 32 + mi * 16 + (lid & 15);
        int e0 = (lid >> 4) ^ ((r >> 1) & 3);
        aAd[mi] = sbase + (uint32_t)(r * 64 + (e0 << 4));
    }
#pragma unroll
    for (int ni = 0; ni < 4; ni++) {
        int r = wn * 64 + ni * 16 + ((lid >> 4) << 3) + (lid & 7);
        int e0 = ((lid >> 3) & 1) ^ ((r >> 1) & 3);
        bAd[ni] = sbase + SB_OFF + (uint32_t)(r * 64 + (e0 << 4));
    }

    float acc[2][8][4];
#pragma unroll
    for (int i = 0; i < 2; i++)
#pragma unroll
        for (int j = 0; j < 8; j++)
#pragma unroll
            for (int k = 0; k < 4; k++) acc[i][j][k] = 0.f;

    // load one BK=64 stage (both sub-chunks), 8 cp.async/thread
    auto load_stage = [&](int kt, int stg) {
#pragma unroll
        for (int c = 0; c < 2; c++) {
            const int k0 = kt * 64 + c * 32;
            const uint32_t so = (uint32_t)(stg * STG2_BYTES + c * SUB_BYTES);
            cpa16(dA[0] + so, gA + k0 + c0 * 8);
            cpa16(dA[1] + so, gA + k0 + (c0 + 1) * 8);
            cpa16(dB[0] + so, gB + k0 + c0 * 8);
            cpa16(dB[1] + so, gB + k0 + (c0 + 1) * 8);
        }
    };

    // ---- prologue: stages 0,1 in flight
    load_stage(0, 0); CP_COMMIT();
    load_stage(1, 1); CP_COMMIT();

    int stg = 0;
    for (int kt = 0; kt < NIT2; ++kt) {
        CP_WAIT1();                 // stage kt resident; kt+1 in flight
        __syncthreads();
        if (kt + 2 < NIT2) load_stage(kt + 2, (stg + 2) % 3);
        CP_COMMIT();                // always commit (group accounting)

#pragma unroll
        for (int c = 0; c < 2; c++) {
            const uint32_t so = (uint32_t)(stg * STG2_BYTES + c * SUB_BYTES);
            uint32_t ar0[2][4], br0[4][4], ar1[2][4], br1[4][4];
            ldsm4(ar0[0], aAd[0] + so);
            ldsm4(ar0[1], aAd[1] + so);
#pragma unroll
            for (int ni = 0; ni < 4; ni++) ldsm4(br0[ni], bAd[ni] + so);
            ldsm4(ar1[0], (aAd[0] + so) ^ 32u);
            ldsm4(ar1[1], (aAd[1] + so) ^ 32u);
#pragma unroll
            for (int mi = 0; mi < 2; mi++)
#pragma unroll
                for (int n8 = 0; n8 < 8; n8++)
                    mma16816(acc[mi][n8], ar0[mi], &br0[n8 >> 1][(n8 & 1) << 1]);
#pragma unroll
            for (int ni = 0; ni < 4; ni++) ldsm4(br1[ni], (bAd[ni] + so) ^ 32u);
#pragma unroll
            for (int mi = 0; mi < 2; mi++)
#pragma unroll
                for (int n8 = 0; n8 < 8; n8++)
                    mma16816(acc[mi][n8], ar1[mi], &br1[n8 >> 1][(n8 & 1) << 1]);
        }
        stg = (stg + 1) % 3;
    }

    // ---- epilogue (R12-best: Q/K hi+lo vectorized, V^T scalar scatter)
    const int row_l = lid >> 2;
    const int col_l = (lid & 3) << 1;
#pragma unroll
    for (int ni = 0; ni < 8; ni++) {
        const int c = n0 + wn * 64 + ni * 8 + col_l;
        const float bx = bias[c], by = bias[c + 1];
#pragma unroll
        for (int mi = 0; mi < 2; mi++) {
            const int r = m0 + wm * 32 + mi * 16 + row_l;
            float x00 = acc[mi][ni][0] + bx, x01 = acc[mi][ni][1] + by;
            float x10 = acc[mi][ni][2] + bx, x11 = acc[mi][ni][3] + by;
            if (MODE == 0) {
                const int part = c >> 10;
                const int hh   = (c & 1023) >> 6;
                const int d    = c & 63;
                const int bb   = r >> 11;
                const int s    = r & 2047;
                const int bhi  = bb * NHEADS + hh;
                if (part < 2) {
                    __half h00, h01, h10, h11, l00, l01, l10, l11;
                    h_split(x00, h00, l00); h_split(x01, h01, l01);
                    h_split(x10, h10, l10); h_split(x11, h11, l11);
                    __half* dh = (part == 0 ? g_qh : g_kh) + ((size_t)bhi * S_LEN + s) * DHEAD + d;
                    __half* dl = (part == 0 ? g_ql : g_kl) + ((size_t)bhi * S_LEN + s) * DHEAD + d;
                    *(__half2*)dh                 = __half2{h00, h01};
                    *(__half2*)(dh + 8 * DHEAD)   = __half2{h10, h11};
                    *(__half2*)dl                 = __half2{l00, l01};
                    *(__half2*)(dl + 8 * DHEAD)   = __half2{l10, l11};
                } else {
                    __half* th = g_vth + ((size_t)bhi * DHEAD + d) * S_LEN + s;
                    th[0] = __float2half_rn(x00); th[S_LEN]     = __float2half_rn(x01);
                    th[8] = __float2half_rn(x10); th[S_LEN + 8] = __float2half_rn(x11);
                }
            } else {
                float* p = out + (size_t)r * DMODEL + c;
                *(float2*)p                = make_float2(x00, x01);
                *(float2*)(p + 8 * DMODEL) = make_float2(x10, x11);
            }
        }
    }
}

// ---------------------------------------------------------------------------
// Tensor-core flash attention (R12-best, verbatim). QK 3-term, PV 2-term.
// smem: Qh 8K | Ql 8K | K 2x(hi 4K + lo 4K) | Vt 2x4K = 40K static.
// ---------------------------------------------------------------------------
#define OFF_QL 8192
#define OFF_K  16384
#define OFF_VT 32768

__global__ __launch_bounds__(128, 3) void attn_kernel()
{
    __shared__ __align__(1024) char smbuf[40960];
    const uint32_t sb = smem_u32(smbuf);
    const int tid = threadIdx.x;
    const int lid = tid & 31, wid = tid >> 5;
    const int q0 = blockIdx.x * 64;
    const int bh = blockIdx.y;
    const int hh = bh & 15, bb = bh >> 4;
    const int nT = min(10, (S_LEN - q0) >> 5);

    const __half* Qhp = g_qh + (size_t)bh * S_LEN * DHEAD;
    const __half* Qlp = g_ql + (size_t)bh * S_LEN * DHEAD;
    const __half* Khp = g_kh + (size_t)bh * S_LEN * DHEAD;
    const __half* Klp = g_kl + (size_t)bh * S_LEN * DHEAD;
    const __half* Vhp = g_vth + (size_t)bh * DHEAD * S_LEN;

    {
        int r = tid >> 1, j0 = (tid & 1) * 4;
        const __half* sh = Qhp + (size_t)(q0 + r) * DHEAD;
        const __half* sl = Qlp + (size_t)(q0 + r) * DHEAD;
        uint32_t rb = sb + r * 128;
#pragma unroll
        for (int j = j0; j < j0 + 4; j++) {
            uint32_t o = (uint32_t)((j ^ (r & 7)) << 4);
            cpa16(rb + o, sh + j * 8);
            cpa16(rb + OFF_QL + o, sl + j * 8);
        }
    }
    CP_COMMIT();

    auto load_tile = [&](int t) {
        int kt0 = q0 + t * 32, s = t & 1;
        {
            int r = tid >> 2, j0 = (tid & 3) * 2;
            const __half* sh = Khp + (size_t)(kt0 + r) * DHEAD;
            const __half* sl = Klp + (size_t)(kt0 + r) * DHEAD;
            uint32_t kb = sb + OFF_K + s * 8192 + r * 128;
#pragma unroll
            for (int j = j0; j < j0 + 2; j++) {
                uint32_t o = (uint32_t)((j ^ (r & 7)) << 4);
                cpa16(kb + o, sh + j * 8);
                cpa16(kb + 4096 + o, sl + j * 8);
            }
        }
        {
            int r = tid >> 1;
            int jj0 = (tid & 1) * 2;
            const __half* sh = Vhp + (size_t)r * S_LEN + kt0;
            uint32_t vb = sb + OFF_VT + s * 4096 + r * 64;
#pragma unroll
            for (int jc = jj0; jc < jj0 + 2; jc++) {
                uint32_t o = (uint32_t)((jc ^ ((r >> 1) & 3)) << 4);
                cpa16(vb + o, sh + jc * 8);
            }
        }
    };
    load_tile(0); CP_COMMIT();
    load_tile(1); CP_COMMIT();
    CP_WAIT1();
    __syncthreads();

    uint32_t qh[4][4], ql[4][4];
    {
        int r = wid * 16 + (lid & 15);
        uint32_t base = (uint32_t)(r * 128 + (((lid >> 4) ^ (r & 7)) << 4));
#pragma unroll
        for (int kc = 0; kc < 4; kc++) {
            ldsm4(qh[kc], (sb + base) ^ (uint32_t)(kc << 5));
            ldsm4(ql[kc], (sb + OFF_QL + base) ^ (uint32_t)(kc << 5));
        }
    }

    uint32_t kadr[2], vadr[4];
#pragma unroll
    for (int ni = 0; ni < 2; ni++) {
        int r = ni * 16 + ((lid >> 4) << 3) + (lid & 7);
        kadr[ni] = (uint32_t)(r * 128 + ((((lid >> 3) & 1) ^ (r & 7)) << 4));
    }
#pragma unroll
    for (int ni = 0; ni < 4; ni++) {
        int r = ni * 16 + ((lid >> 4) << 3) + (lid & 7);
        vadr[ni] = (uint32_t)(r * 64 + ((((lid >> 3) & 1) ^ ((r >> 1) & 3)) << 4));
    }

    float od[8][4];
#pragma unroll
    for (int i = 0; i < 8; i++) { od[i][0] = od[i][1] = od[i][2] = od[i][3] = 0.f; }
    float m0 = -1e30f, m1 = -1e30f, l0 = 0.f, l1 = 0.f;
    const int qr0 = q0 + wid * 16 + (lid >> 2);
    const int qr1 = qr0 + 8;
    const int kcol = (lid & 3) << 1;
    const int wlo = q0 + wid * 16;

    for (int t = 0; t < nT; ++t) {
        const int kt0 = q0 + t * 32, s = t & 1;
        const bool active = (kt0 + 31 >= wlo) && (kt0 <= wlo + 15 + WIN - 1);
        if (active) {
            float sc[4][4];
#pragma unroll
            for (int i = 0; i < 4; i++) { sc[i][0] = sc[i][1] = sc[i][2] = sc[i][3] = 0.f; }
            const uint32_t kbh = sb + OFF_K + s * 8192;
            const uint32_t kbl = kbh + 4096;
#pragma unroll
            for (int kc = 0; kc < 4; kc++) {
                const uint32_t kx = (uint32_t)(kc << 5);
                uint32_t kh2[2][4], kl2[2][4];
                ldsm4(kh2[0], (kbh + kadr[0]) ^ kx);
                ldsm4(kh2[1], (kbh + kadr[1]) ^ kx);
                ldsm4(kl2[0], (kbl + kadr[0]) ^ kx);
                ldsm4(kl2[1], (kbl + kadr[1]) ^ kx);
#pragma unroll
                for (int ni = 0; ni < 2; ni++)
#pragma unroll
                    for (int hf = 0; hf < 2; hf++) {
                        int n8 = ni * 2 + hf;
                        mma16816(sc[n8], qh[kc], &kh2[ni][hf * 2]);
                        mma16816(sc[n8], ql[kc], &kh2[ni][hf * 2]);
                        mma16816(sc[n8], qh[kc], &kl2[ni][hf * 2]);
                    }
            }
#pragma unroll
            for (int n8 = 0; n8 < 4; n8++) {
#pragma unroll
                for (int jj = 0; jj < 2; jj++) {
                    int key = kt0 + n8 * 8 + kcol + jj;
                    sc[n8][jj]     = (key >= qr0 && key < qr0 + WIN) ? sc[n8][jj] * ATT_SCALE : -INFINITY;
                    sc[n8][2 + jj] = (key >= qr1 && key < qr1 + WIN) ? sc[n8][2 + jj] * ATT_SCALE : -INFINITY;
                }
            }
            float t0 = fmaxf(fmaxf(sc[0][0], sc[0][1]), fmaxf(sc[1][0], sc[1][1]));
            t0 = fmaxf(t0, fmaxf(fmaxf(sc[2][0], sc[2][1]), fmaxf(sc[3][0], sc[3][1])));
            float t1 = fmaxf(fmaxf(sc[0][2], sc[0][3]), fmaxf(sc[1][2], sc[1][3]));
            t1 = fmaxf(t1, fmaxf(fmaxf(sc[2][2], sc[2][3]), fmaxf(sc[3][2], sc[3][3])));
            t0 = fmaxf(t0, __shfl_xor_sync(0xffffffffu, t0, 1));
            t0 = fmaxf(t0, __shfl_xor_sync(0xffffffffu, t0, 2));
            t1 = fmaxf(t1, __shfl_xor_sync(0xffffffffu, t1, 1));
            t1 = fmaxf(t1, __shfl_xor_sync(0xffffffffu, t1, 2));
            float nm0 = fmaxf(m0, t0), nm1 = fmaxf(m1, t1);
            float f0 = __expf(m0 - nm0), f1 = __expf(m1 - nm1);
            m0 = nm0; m1 = nm1;
            float s0 = 0.f, s1 = 0.f;
#pragma unroll
            for (int n8 = 0; n8 < 4; n8++) {
                sc[n8][0] = __expf(sc[n8][0] - nm0); s0 += sc[n8][0];
                sc[n8][1] = __expf(sc[n8][1] - nm0); s0 += sc[n8][1];
                sc[n8][2] = __expf(sc[n8][2] - nm1); s1 += sc[n8][2];
                sc[n8][3] = __expf(sc[n8][3] - nm1); s1 += sc[n8][3];
            }
            s0 += __shfl_xor_sync(0xffffffffu, s0, 1);
            s0 += __shfl_xor_sync(0xffffffffu, s0, 2);
            s1 += __shfl_xor_sync(0xffffffffu, s1, 1);
            s1 += __shfl_xor_sync(0xffffffffu, s1, 2);
            l0 = l0 * f0 + s0; l1 = l1 * f1 + s1;
#pragma unroll
            for (int n8 = 0; n8 < 8; n8++) {
                od[n8][0] *= f0; od[n8][1] *= f0;
                od[n8][2] *= f1; od[n8][3] *= f1;
            }
            uint32_t ph[2][4], pl[2][4];
#pragma unroll
            for (int kp = 0; kp < 2; kp++)
#pragma unroll
                for (int rg = 0; rg < 4; rg++) {
                    int n8 = kp * 2 + (rg >> 1);
                    float pa = sc[n8][(rg & 1) * 2 + 0];
                    float pb = sc[n8][(rg & 1) * 2 + 1];
                    __half ha = __float2half_rn(pa), hb = __float2half_rn(pb);
                    ph[kp][rg] = ((uint32_t)__half_as_ushort(hb) << 16) | __half_as_ushort(ha);
                    __half la = __float2half_rn(pa - __half2float(ha));
                    __half lb = __float2half_rn(pb - __half2float(hb));
                    pl[kp][rg] = ((uint32_t)__half_as_ushort(lb) << 16) | __half_as_ushort(la);
                }
            const uint32_t vbh = sb + OFF_VT + s * 4096;
#pragma unroll
            for (int kp = 0; kp < 2; kp++) {
                const uint32_t kx = (uint32_t)(kp << 5);
                uint32_t vh2[4][4];
#pragma unroll
                for (int ni = 0; ni < 4; ni++)
                    ldsm4(vh2[ni], (vbh + vadr[ni]) ^ kx);
#pragma unroll
                for (int ni = 0; ni < 4; ni++)
#pragma unroll
                    for (int hf = 0; hf < 2; hf++) {
                        int n8 = ni * 2 + hf;
                        mma16816(od[n8], ph[kp], &vh2[ni][hf * 2]);
                        mma16816(od[n8], pl[kp], &vh2[ni][hf * 2]);
                    }
            }
        }
        __syncthreads();
        if (t + 1 < nT) {
            if (t + 2 < nT) { load_tile(t + 2); CP_COMMIT(); CP_WAIT1(); }
            else            { CP_WAIT0(); }
            __syncthreads();
        }
    }

    const float inv0 = 1.0f / l0, inv1 = 1.0f / l1;
    const size_t o0 = ((size_t)(bb * S_LEN + qr0)) * KD + hh * 64;
    const size_t o1 = ((size_t)(bb * S_LEN + qr1)) * KD + hh * 64;
#pragma unroll
    for (int n8 = 0; n8 < 8; n8++) {
        int d = n8 * 8 + kcol;
        *(__half2*)(g_ch + o0 + d) =
            __half2{__float2half_rn(od[n8][0] * inv0), __float2half_rn(od[n8][1] * inv0)};
        *(__half2*)(g_ch + o1 + d) =
            __half2{__float2half_rn(od[n8][2] * inv1), __float2half_rn(od[n8][3] * inv1)};
    }
}

// ---------------------------------------------------------------------------
extern "C" void kernel_launch(void* const* d_in, const int* in_sizes, int n_in,
                              void* d_out, int out_size)
{
    const float* x    = (const float*)d_in[0];
    const float* Wqkv = (const float*)d_in[1];
    const float* bqkv = (const float*)d_in[2];
    const float* Wout = (const float*)d_in[3];
    const float* bout = (const float*)d_in[4];
    float* out = (float*)d_out;
    (void)in_sizes; (void)n_in; (void)out_size;

    cudaFuncSetAttribute(mma_gemm_kernel<0>, cudaFuncAttributeMaxDynamicSharedMemorySize, SMEM_DYN);
    cudaFuncSetAttribute(mma_gemm_kernel<1>, cudaFuncAttributeMaxDynamicSharedMemorySize, SMEM_DYN);

    conv_x_kernel<<<MROWS * KD / 4 / 256, 256>>>(x);
    wconv_all_kernel<<<dim3(128, DMODEL / 32), dim3(32, 8)>>>(Wqkv, Wout);

    // QKV projection: M=4096, N=3072, K=1024 (fp16 mma.sync, BK=64, 3 stages)
    mma_gemm_kernel<0><<<dim3(3 * DMODEL / BN, MROWS / BM), 256, SMEM_DYN>>>(bqkv, nullptr);
    // Tensor-core flash attention -> g_ch
    attn_kernel<<<dim3(S_LEN / 64, BH), 128>>>();
    // Output projection: M=4096, N=1024, K=1024
    mma_gemm_kernel<1><<<dim3(DMODEL / BN, MROWS / BM), 256, SMEM_DYN>>>(bout, out);
}

// round 16
// speedup vs baseline: 1.0953x; 1.0953x over previous
#include <cuda_runtime.h>
#include <cuda_fp16.h>
#include <math.h>
#include <stdint.h>

#define S_LEN 2048
#define DMODEL 1024
#define NHEADS 16
#define DHEAD 64
#define WIN 256
#define BATCH 2
#define BH (BATCH * NHEADS)
#define MROWS (BATCH * S_LEN)
#define KD 1024
#define ATT_SCALE 0.125f

// ---- mma.sync / ldmatrix / cp.async helpers (baseline PTX) ----
__device__ __forceinline__ uint32_t smem_u32(const void* p) {
    uint32_t a;
    asm("{ .reg .u64 t; cvta.to.shared.u64 t, %1; cvt.u32.u64 %0, t; }" : "=r"(a) : "l"(p));
    return a;
}
__device__ __forceinline__ void ldsm4(uint32_t* r, uint32_t addr) {
    asm volatile("ldmatrix.sync.aligned.m8n8.x4.shared.b16 {%0,%1,%2,%3}, [%4];"
                 : "=r"(r[0]), "=r"(r[1]), "=r"(r[2]), "=r"(r[3]) : "r"(addr));
}
__device__ __forceinline__ void mma16816(float* d, const uint32_t* a, const uint32_t* b) {
    asm volatile("mma.sync.aligned.m16n8k16.row.col.f32.f16.f16.f32 "
        "{%0,%1,%2,%3}, {%4,%5,%6,%7}, {%8,%9}, {%0,%1,%2,%3};"
        : "+f"(d[0]), "+f"(d[1]), "+f"(d[2]), "+f"(d[3])
        : "r"(a[0]), "r"(a[1]), "r"(a[2]), "r"(a[3]), "r"(b[0]), "r"(b[1]));
}
__device__ __forceinline__ void cpa16(uint32_t dst, const void* src) {
    asm volatile("cp.async.cg.shared.global [%0], [%1], 16;" :: "r"(dst), "l"(src));
}
#define CP_COMMIT() asm volatile("cp.async.commit_group;" ::: "memory")
#define CP_WAIT0()  asm volatile("cp.async.wait_group 0;" ::: "memory")
#define CP_WAIT1()  asm volatile("cp.async.wait_group 1;" ::: "memory")
#define CP_WAIT2()  asm volatile("cp.async.wait_group 2;" ::: "memory")

// Scratch (allocation-free rule: __device__ globals)
__device__ __half g_xh[(size_t)MROWS * KD];           // fp16 x
__device__ __half g_ch[(size_t)MROWS * KD];           // fp16 attention out
__device__ __half g_wqh[(size_t)(3 * DMODEL) * KD];   // W_qkv^T fp16 [3072][1024]
__device__ __half g_woh[(size_t)DMODEL * KD];         // W_out^T fp16 [1024][1024]
__device__ __half g_qh[(size_t)BH * S_LEN * DHEAD];   // Q hi  [bh][s][d]
__device__ __half g_ql[(size_t)BH * S_LEN * DHEAD];   // Q lo
__device__ __half g_kh[(size_t)BH * S_LEN * DHEAD];   // K hi
__device__ __half g_kl[(size_t)BH * S_LEN * DHEAD];   // K lo
__device__ __half g_vth[(size_t)BH * DHEAD * S_LEN];  // V^T hi [bh][d][s]

__device__ __forceinline__ void h_split(float v, __half& hi, __half& lo) {
    hi = __float2half_rn(v);
    lo = __float2half_rn(v - __half2float(hi));
}

// ---------------------------------------------------------------------------
// Convert x [4096][1024] f32 -> g_xh fp16
// ---------------------------------------------------------------------------
__global__ __launch_bounds__(256) void conv_x_kernel(const float* __restrict__ src)
{
    int idx = blockIdx.x * 256 + threadIdx.x;
    int m = idx >> 8;
    int c = (idx & 255) << 2;
    float4 v = *(const float4*)(src + (size_t)m * KD + c);
    size_t o = (size_t)m * KD + c;
    *(__half2*)(g_xh + o)     = __half2{__float2half_rn(v.x), __float2half_rn(v.y)};
    *(__half2*)(g_xh + o + 2) = __half2{__float2half_rn(v.z), __float2half_rn(v.w)};
}

// ---------------------------------------------------------------------------
// Transpose + fp16 convert BOTH weights in one launch.
// blocks [0,96): Wqkv (NC=3072) -> g_wqh; blocks [96,128): Wout -> g_woh.
// ---------------------------------------------------------------------------
__global__ __launch_bounds__(256) void wconv_all_kernel(
    const float* __restrict__ Wq, const float* __restrict__ Wo)
{
    __shared__ float tile[32][33];
    const int bx = blockIdx.x;
    const float* src; __half* dst; int NC, n0;
    if (bx < 96) { src = Wq; dst = g_wqh; NC = 3072; n0 = bx * 32; }
    else         { src = Wo; dst = g_woh; NC = 1024; n0 = (bx - 96) * 32; }
    int k0 = blockIdx.y * 32;
    int tx = threadIdx.x, ty = threadIdx.y;   // 32 x 8
#pragma unroll
    for (int i = 0; i < 32; i += 8)
        tile[ty + i][tx] = src[(size_t)(k0 + ty + i) * NC + n0 + tx];
    __syncthreads();
#pragma unroll
    for (int i = 0; i < 32; i += 8) {
        float v = tile[tx][ty + i];
        int n = n0 + ty + i, k = k0 + tx;
        dst[(size_t)n * KD + k] = __float2half_rn(v);
    }
}

// ---------------------------------------------------------------------------
// fp16 mma.sync GEMM (R12-exact: 256 thr, 8 warps, 32x64 warp tiles, BK=32,
// 4-stage cp.async, software-pipelined fragments).
// MODE 0: A=g_xh B=g_wqh; epilogue Q/K hi+lo, V^T scalar scatter.
// MODE 1: A=g_ch B=g_woh -> fp32 out.
// ---------------------------------------------------------------------------
#define BM 128
#define BN 128
#define BK 32
#define NIT 32
#define SB_OFF 8192
#define STG_BYTES 16384
#define SMEM_DYN (4 * STG_BYTES)

template <int MODE>
__global__ __launch_bounds__(256, 2) void mma_gemm_kernel(
    const float* __restrict__ bias, float* __restrict__ out)
{
    extern __shared__ char dsm[];
    const __half* __restrict__ Ah = MODE ? g_ch : g_xh;
    const __half* __restrict__ Bh = MODE ? g_woh : g_wqh;

    const int tid = threadIdx.x;
    const int wid = tid >> 5, lid = tid & 31;
    const int m0 = blockIdx.y * BM, n0 = blockIdx.x * BN;
    const int wm = wid & 3, wn = wid >> 2;       // 4x2 warp grid, 32x64 tiles
    const uint32_t sbase = smem_u32(dsm);

    const int row = tid >> 1;
    const int c0  = (tid & 1) << 1;
    const int sw  = (row >> 1) & 3;
    const __half* gA = Ah + (size_t)(m0 + row) * KD;
    const __half* gB = Bh + (size_t)(n0 + row) * KD;
    uint32_t dA[2], dB[2];
#pragma unroll
    for (int j = 0; j < 2; j++) {
        dA[j] = sbase + (uint32_t)(row * 64 + (((c0 + j) ^ sw) << 4));
        dB[j] = dA[j] + SB_OFF;
    }

    uint32_t aAd[2], bAd[4];
#pragma unroll
    for (int mi = 0; mi < 2; mi++) {
        int r = wm * 32 + mi * 16 + (lid & 15);
        int e0 = (lid >> 4) ^ ((r >> 1) & 3);
        aAd[mi] = sbase + (uint32_t)(r * 64 + (e0 << 4));
    }
#pragma unroll
    for (int ni = 0; ni < 4; ni++) {
        int r = wn * 64 + ni * 16 + ((lid >> 4) << 3) + (lid & 7);
        int e0 = ((lid >> 3) & 1) ^ ((r >> 1) & 3);
        bAd[ni] = sbase + SB_OFF + (uint32_t)(r * 64 + (e0 << 4));
    }

    float acc[2][8][4];
#pragma unroll
    for (int i = 0; i < 2; i++)
#pragma unroll
        for (int j = 0; j < 8; j++)
#pragma unroll
            for (int k = 0; k < 4; k++) acc[i][j][k] = 0.f;

#pragma unroll
    for (int s = 0; s < 3; s++) {
        const int k0 = s * BK;
        const uint32_t so = s * STG_BYTES;
        cpa16(dA[0] + so, gA + k0 + c0 * 8);
        cpa16(dA[1] + so, gA + k0 + (c0 + 1) * 8);
        cpa16(dB[0] + so, gB + k0 + c0 * 8);
        cpa16(dB[1] + so, gB + k0 + (c0 + 1) * 8);
        CP_COMMIT();
    }

    for (int kt = 0; kt < NIT; ++kt) {
        CP_WAIT2();
        __syncthreads();
        if (kt + 3 < NIT) {
            const int k0 = (kt + 3) * BK;
            const uint32_t so = ((kt + 3) & 3) * STG_BYTES;
            cpa16(dA[0] + so, gA + k0 + c0 * 8);
            cpa16(dA[1] + so, gA + k0 + (c0 + 1) * 8);
            cpa16(dB[0] + so, gB + k0 + c0 * 8);
            cpa16(dB[1] + so, gB + k0 + (c0 + 1) * 8);
        }
        CP_COMMIT();

        const uint32_t so = (kt & 3) * STG_BYTES;
        uint32_t ar0[2][4], br0[4][4], ar1[2][4], br1[4][4];
        ldsm4(ar0[0], aAd[0] + so);
        ldsm4(ar0[1], aAd[1] + so);
#pragma unroll
        for (int ni = 0; ni < 4; ni++) ldsm4(br0[ni], bAd[ni] + so);
        ldsm4(ar1[0], (aAd[0] + so) ^ 32u);
        ldsm4(ar1[1], (aAd[1] + so) ^ 32u);
#pragma unroll
        for (int mi = 0; mi < 2; mi++)
#pragma unroll
            for (int n8 = 0; n8 < 8; n8++)
                mma16816(acc[mi][n8], ar0[mi], &br0[n8 >> 1][(n8 & 1) << 1]);
#pragma unroll
        for (int ni = 0; ni < 4; ni++) ldsm4(br1[ni], (bAd[ni] + so) ^ 32u);
#pragma unroll
        for (int mi = 0; mi < 2; mi++)
#pragma unroll
            for (int n8 = 0; n8 < 8; n8++)
                mma16816(acc[mi][n8], ar1[mi], &br1[n8 >> 1][(n8 & 1) << 1]);
    }

    // ---- epilogue
    const int row_l = lid >> 2;
    const int col_l = (lid & 3) << 1;
#pragma unroll
    for (int ni = 0; ni < 8; ni++) {
        const int c = n0 + wn * 64 + ni * 8 + col_l;
        const float bx = bias[c], by = bias[c + 1];
#pragma unroll
        for (int mi = 0; mi < 2; mi++) {
            const int r = m0 + wm * 32 + mi * 16 + row_l;
            float x00 = acc[mi][ni][0] + bx, x01 = acc[mi][ni][1] + by;
            float x10 = acc[mi][ni][2] + bx, x11 = acc[mi][ni][3] + by;
            if (MODE == 0) {
                const int part = c >> 10;
                const int hh   = (c & 1023) >> 6;
                const int d    = c & 63;
                const int bb   = r >> 11;
                const int s    = r & 2047;
                const int bhi  = bb * NHEADS + hh;
                if (part < 2) {
                    __half h00, h01, h10, h11, l00, l01, l10, l11;
                    h_split(x00, h00, l00); h_split(x01, h01, l01);
                    h_split(x10, h10, l10); h_split(x11, h11, l11);
                    __half* dh = (part == 0 ? g_qh : g_kh) + ((size_t)bhi * S_LEN + s) * DHEAD + d;
                    __half* dl = (part == 0 ? g_ql : g_kl) + ((size_t)bhi * S_LEN + s) * DHEAD + d;
                    *(__half2*)dh                 = __half2{h00, h01};
                    *(__half2*)(dh + 8 * DHEAD)   = __half2{h10, h11};
                    *(__half2*)dl                 = __half2{l00, l01};
                    *(__half2*)(dl + 8 * DHEAD)   = __half2{l10, l11};
                } else {
                    __half* th = g_vth + ((size_t)bhi * DHEAD + d) * S_LEN + s;
                    th[0] = __float2half_rn(x00); th[S_LEN]     = __float2half_rn(x01);
                    th[8] = __float2half_rn(x10); th[S_LEN + 8] = __float2half_rn(x11);
                }
            } else {
                float* p = out + (size_t)r * DMODEL + c;
                *(float2*)p                = make_float2(x00, x01);
                *(float2*)(p + 8 * DMODEL) = make_float2(x10, x11);
            }
        }
    }
}

// ---------------------------------------------------------------------------
// Tensor-core flash attention. QK 3-term (Qh.Kh + Ql.Kh + Qh.Kl),
// PV 1-term (Ph.Vh) — P-lo dropped this round.
// smem: Qh 8K | Ql 8K | K 2x(hi 4K + lo 4K) | Vt 2x4K = 40K static.
// ---------------------------------------------------------------------------
#define OFF_QL 8192
#define OFF_K  16384
#define OFF_VT 32768

__global__ __launch_bounds__(128, 3) void attn_kernel()
{
    __shared__ __align__(1024) char smbuf[40960];
    const uint32_t sb = smem_u32(smbuf);
    const int tid = threadIdx.x;
    const int lid = tid & 31, wid = tid >> 5;
    const int q0 = blockIdx.x * 64;
    const int bh = blockIdx.y;
    const int hh = bh & 15, bb = bh >> 4;
    const int nT = min(10, (S_LEN - q0) >> 5);

    const __half* Qhp = g_qh + (size_t)bh * S_LEN * DHEAD;
    const __half* Qlp = g_ql + (size_t)bh * S_LEN * DHEAD;
    const __half* Khp = g_kh + (size_t)bh * S_LEN * DHEAD;
    const __half* Klp = g_kl + (size_t)bh * S_LEN * DHEAD;
    const __half* Vhp = g_vth + (size_t)bh * DHEAD * S_LEN;

    {
        int r = tid >> 1, j0 = (tid & 1) * 4;
        const __half* sh = Qhp + (size_t)(q0 + r) * DHEAD;
        const __half* sl = Qlp + (size_t)(q0 + r) * DHEAD;
        uint32_t rb = sb + r * 128;
#pragma unroll
        for (int j = j0; j < j0 + 4; j++) {
            uint32_t o = (uint32_t)((j ^ (r & 7)) << 4);
            cpa16(rb + o, sh + j * 8);
            cpa16(rb + OFF_QL + o, sl + j * 8);
        }
    }
    CP_COMMIT();

    auto load_tile = [&](int t) {
        int kt0 = q0 + t * 32, s = t & 1;
        {
            int r = tid >> 2, j0 = (tid & 3) * 2;
            const __half* sh = Khp + (size_t)(kt0 + r) * DHEAD;
            const __half* sl = Klp + (size_t)(kt0 + r) * DHEAD;
            uint32_t kb = sb + OFF_K + s * 8192 + r * 128;
#pragma unroll
            for (int j = j0; j < j0 + 2; j++) {
                uint32_t o = (uint32_t)((j ^ (r & 7)) << 4);
                cpa16(kb + o, sh + j * 8);
                cpa16(kb + 4096 + o, sl + j * 8);
            }
        }
        {
            int r = tid >> 1;
            int jj0 = (tid & 1) * 2;
            const __half* sh = Vhp + (size_t)r * S_LEN + kt0;
            uint32_t vb = sb + OFF_VT + s * 4096 + r * 64;
#pragma unroll
            for (int jc = jj0; jc < jj0 + 2; jc++) {
                uint32_t o = (uint32_t)((jc ^ ((r >> 1) & 3)) << 4);
                cpa16(vb + o, sh + jc * 8);
            }
        }
    };
    load_tile(0); CP_COMMIT();
    load_tile(1); CP_COMMIT();
    CP_WAIT1();
    __syncthreads();

    uint32_t qh[4][4], ql[4][4];
    {
        int r = wid * 16 + (lid & 15);
        uint32_t base = (uint32_t)(r * 128 + (((lid >> 4) ^ (r & 7)) << 4));
#pragma unroll
        for (int kc = 0; kc < 4; kc++) {
            ldsm4(qh[kc], (sb + base) ^ (uint32_t)(kc << 5));
            ldsm4(ql[kc], (sb + OFF_QL + base) ^ (uint32_t)(kc << 5));
        }
    }

    uint32_t kadr[2], vadr[4];
#pragma unroll
    for (int ni = 0; ni < 2; ni++) {
        int r = ni * 16 + ((lid >> 4) << 3) + (lid & 7);
        kadr[ni] = (uint32_t)(r * 128 + ((((lid >> 3) & 1) ^ (r & 7)) << 4));
    }
#pragma unroll
    for (int ni = 0; ni < 4; ni++) {
        int r = ni * 16 + ((lid >> 4) << 3) + (lid & 7);
        vadr[ni] = (uint32_t)(r * 64 + ((((lid >> 3) & 1) ^ ((r >> 1) & 3)) << 4));
    }

    float od[8][4];
#pragma unroll
    for (int i = 0; i < 8; i++) { od[i][0] = od[i][1] = od[i][2] = od[i][3] = 0.f; }
    float m0 = -1e30f, m1 = -1e30f, l0 = 0.f, l1 = 0.f;
    const int qr0 = q0 + wid * 16 + (lid >> 2);
    const int qr1 = qr0 + 8;
    const int kcol = (lid & 3) << 1;
    const int wlo = q0 + wid * 16;

    for (int t = 0; t < nT; ++t) {
        const int kt0 = q0 + t * 32, s = t & 1;
        const bool active = (kt0 + 31 >= wlo) && (kt0 <= wlo + 15 + WIN - 1);
        if (active) {
            float sc[4][4];
#pragma unroll
            for (int i = 0; i < 4; i++) { sc[i][0] = sc[i][1] = sc[i][2] = sc[i][3] = 0.f; }
            const uint32_t kbh = sb + OFF_K + s * 8192;
            const uint32_t kbl = kbh + 4096;
#pragma unroll
            for (int kc = 0; kc < 4; kc++) {
                const uint32_t kx = (uint32_t)(kc << 5);
                uint32_t kh2[2][4], kl2[2][4];
                ldsm4(kh2[0], (kbh + kadr[0]) ^ kx);
                ldsm4(kh2[1], (kbh + kadr[1]) ^ kx);
                ldsm4(kl2[0], (kbl + kadr[0]) ^ kx);
                ldsm4(kl2[1], (kbl + kadr[1]) ^ kx);
#pragma unroll
                for (int ni = 0; ni < 2; ni++)
#pragma unroll
                    for (int hf = 0; hf < 2; hf++) {
                        int n8 = ni * 2 + hf;
                        mma16816(sc[n8], qh[kc], &kh2[ni][hf * 2]);
                        mma16816(sc[n8], ql[kc], &kh2[ni][hf * 2]);
                        mma16816(sc[n8], qh[kc], &kl2[ni][hf * 2]);
                    }
            }
#pragma unroll
            for (int n8 = 0; n8 < 4; n8++) {
#pragma unroll
                for (int jj = 0; jj < 2; jj++) {
                    int key = kt0 + n8 * 8 + kcol + jj;
                    sc[n8][jj]     = (key >= qr0 && key < qr0 + WIN) ? sc[n8][jj] * ATT_SCALE : -INFINITY;
                    sc[n8][2 + jj] = (key >= qr1 && key < qr1 + WIN) ? sc[n8][2 + jj] * ATT_SCALE : -INFINITY;
                }
            }
            float t0 = fmaxf(fmaxf(sc[0][0], sc[0][1]), fmaxf(sc[1][0], sc[1][1]));
            t0 = fmaxf(t0, fmaxf(fmaxf(sc[2][0], sc[2][1]), fmaxf(sc[3][0], sc[3][1])));
            float t1 = fmaxf(fmaxf(sc[0][2], sc[0][3]), fmaxf(sc[1][2], sc[1][3]));
            t1 = fmaxf(t1, fmaxf(fmaxf(sc[2][2], sc[2][3]), fmaxf(sc[3][2], sc[3][3])));
            t0 = fmaxf(t0, __shfl_xor_sync(0xffffffffu, t0, 1));
            t0 = fmaxf(t0, __shfl_xor_sync(0xffffffffu, t0, 2));
            t1 = fmaxf(t1, __shfl_xor_sync(0xffffffffu, t1, 1));
            t1 = fmaxf(t1, __shfl_xor_sync(0xffffffffu, t1, 2));
            float nm0 = fmaxf(m0, t0), nm1 = fmaxf(m1, t1);
            float f0 = __expf(m0 - nm0), f1 = __expf(m1 - nm1);
            m0 = nm0; m1 = nm1;
            float s0 = 0.f, s1 = 0.f;
#pragma unroll
            for (int n8 = 0; n8 < 4; n8++) {
                sc[n8][0] = __expf(sc[n8][0] - nm0); s0 += sc[n8][0];
                sc[n8][1] = __expf(sc[n8][1] - nm0); s0 += sc[n8][1];
                sc[n8][2] = __expf(sc[n8][2] - nm1); s1 += sc[n8][2];
                sc[n8][3] = __expf(sc[n8][3] - nm1); s1 += sc[n8][3];
            }
            s0 += __shfl_xor_sync(0xffffffffu, s0, 1);
            s0 += __shfl_xor_sync(0xffffffffu, s0, 2);
            s1 += __shfl_xor_sync(0xffffffffu, s1, 1);
            s1 += __shfl_xor_sync(0xffffffffu, s1, 2);
            l0 = l0 * f0 + s0; l1 = l1 * f1 + s1;
#pragma unroll
            for (int n8 = 0; n8 < 8; n8++) {
                od[n8][0] *= f0; od[n8][1] *= f0;
                od[n8][2] *= f1; od[n8][3] *= f1;
            }
            // ---- P fragments (hi only; P-lo dropped)
            uint32_t ph[2][4];
#pragma unroll
            for (int kp = 0; kp < 2; kp++)
#pragma unroll
                for (int rg = 0; rg < 4; rg++) {
                    int n8 = kp * 2 + (rg >> 1);
                    float pa = sc[n8][(rg & 1) * 2 + 0];
                    float pb = sc[n8][(rg & 1) * 2 + 1];
                    __half ha = __float2half_rn(pa), hb = __float2half_rn(pb);
                    ph[kp][rg] = ((uint32_t)__half_as_ushort(hb) << 16) | __half_as_ushort(ha);
                }
            const uint32_t vbh = sb + OFF_VT + s * 4096;
#pragma unroll
            for (int kp = 0; kp < 2; kp++) {
                const uint32_t kx = (uint32_t)(kp << 5);
                uint32_t vh2[4][4];
#pragma unroll
                for (int ni = 0; ni < 4; ni++)
                    ldsm4(vh2[ni], (vbh + vadr[ni]) ^ kx);
#pragma unroll
                for (int ni = 0; ni < 4; ni++)
#pragma unroll
                    for (int hf = 0; hf < 2; hf++) {
                        int n8 = ni * 2 + hf;
                        mma16816(od[n8], ph[kp], &vh2[ni][hf * 2]);
                    }
            }
        }
        __syncthreads();
        if (t + 1 < nT) {
            if (t + 2 < nT) { load_tile(t + 2); CP_COMMIT(); CP_WAIT1(); }
            else            { CP_WAIT0(); }
            __syncthreads();
        }
    }

    const float inv0 = 1.0f / l0, inv1 = 1.0f / l1;
    const size_t o0 = ((size_t)(bb * S_LEN + qr0)) * KD + hh * 64;
    const size_t o1 = ((size_t)(bb * S_LEN + qr1)) * KD + hh * 64;
#pragma unroll
    for (int n8 = 0; n8 < 8; n8++) {
        int d = n8 * 8 + kcol;
        *(__half2*)(g_ch + o0 + d) =
            __half2{__float2half_rn(od[n8][0] * inv0), __float2half_rn(od[n8][1] * inv0)};
        *(__half2*)(g_ch + o1 + d) =
            __half2{__float2half_rn(od[n8][2] * inv1), __float2half_rn(od[n8][3] * inv1)};
    }
}

// ---------------------------------------------------------------------------
extern "C" void kernel_launch(void* const* d_in, const int* in_sizes, int n_in,
                              void* d_out, int out_size)
{
    const float* x    = (const float*)d_in[0];
    const float* Wqkv = (const float*)d_in[1];
    const float* bqkv = (const float*)d_in[2];
    const float* Wout = (const float*)d_in[3];
    const float* bout = (const float*)d_in[4];
    float* out = (float*)d_out;
    (void)in_sizes; (void)n_in; (void)out_size;

    cudaFuncSetAttribute(mma_gemm_kernel<0>, cudaFuncAttributeMaxDynamicSharedMemorySize, SMEM_DYN);
    cudaFuncSetAttribute(mma_gemm_kernel<1>, cudaFuncAttributeMaxDynamicSharedMemorySize, SMEM_DYN);

    conv_x_kernel<<<MROWS * KD / 4 / 256, 256>>>(x);
    wconv_all_kernel<<<dim3(128, DMODEL / 32), dim3(32, 8)>>>(Wqkv, Wout);

    // QKV projection: M=4096, N=3072, K=1024 (fp16 mma.sync, BK=32, 4 stages)
    mma_gemm_kernel<0><<<dim3(3 * DMODEL / BN, MROWS / BM), 256, SMEM_DYN>>>(bqkv, nullptr);
    // Tensor-core flash attention -> g_ch
    attn_kernel<<<dim3(S_LEN / 64, BH), 128>>>();
    // Output projection: M=4096, N=1024, K=1024
    mma_gemm_kernel<1><<<dim3(DMODEL / BN, MROWS / BM), 256, SMEM_DYN>>>(bout, out);
}

// round 17
// speedup vs baseline: 1.1113x; 1.0146x over previous
#include <cuda_runtime.h>
#include <cuda_fp16.h>
#include <math.h>
#include <stdint.h>

#define S_LEN 2048
#define DMODEL 1024
#define NHEADS 16
#define DHEAD 64
#define WIN 256
#define BATCH 2
#define BH (BATCH * NHEADS)
#define MROWS (BATCH * S_LEN)
#define KD 1024
#define SCALE_L2E 0.18033688011112042f   // 0.125 * log2(e)

// ---- mma.sync / ldmatrix / cp.async helpers (baseline PTX) ----
__device__ __forceinline__ uint32_t smem_u32(const void* p) {
    uint32_t a;
    asm("{ .reg .u64 t; cvta.to.shared.u64 t, %1; cvt.u32.u64 %0, t; }" : "=r"(a) : "l"(p));
    return a;
}
__device__ __forceinline__ void ldsm4(uint32_t* r, uint32_t addr) {
    asm volatile("ldmatrix.sync.aligned.m8n8.x4.shared.b16 {%0,%1,%2,%3}, [%4];"
                 : "=r"(r[0]), "=r"(r[1]), "=r"(r[2]), "=r"(r[3]) : "r"(addr));
}
__device__ __forceinline__ void mma16816(float* d, const uint32_t* a, const uint32_t* b) {
    asm volatile("mma.sync.aligned.m16n8k16.row.col.f32.f16.f16.f32 "
        "{%0,%1,%2,%3}, {%4,%5,%6,%7}, {%8,%9}, {%0,%1,%2,%3};"
        : "+f"(d[0]), "+f"(d[1]), "+f"(d[2]), "+f"(d[3])
        : "r"(a[0]), "r"(a[1]), "r"(a[2]), "r"(a[3]), "r"(b[0]), "r"(b[1]));
}
__device__ __forceinline__ void cpa16(uint32_t dst, const void* src) {
    asm volatile("cp.async.cg.shared.global [%0], [%1], 16;" :: "r"(dst), "l"(src));
}
#define CP_COMMIT() asm volatile("cp.async.commit_group;" ::: "memory")
#define CP_WAIT0()  asm volatile("cp.async.wait_group 0;" ::: "memory")
#define CP_WAIT1()  asm volatile("cp.async.wait_group 1;" ::: "memory")
#define CP_WAIT2()  asm volatile("cp.async.wait_group 2;" ::: "memory")

// Scratch (allocation-free rule: __device__ globals)
__device__ __half g_xh[(size_t)MROWS * KD];           // fp16 x
__device__ __half g_ch[(size_t)MROWS * KD];           // fp16 attention out
__device__ __half g_wqh[(size_t)(3 * DMODEL) * KD];   // W_qkv^T fp16 [3072][1024]
__device__ __half g_woh[(size_t)DMODEL * KD];         // W_out^T fp16 [1024][1024]
__device__ __half g_qh[(size_t)BH * S_LEN * DHEAD];   // Q hi (pre-scaled by 0.125*log2e)
__device__ __half g_ql[(size_t)BH * S_LEN * DHEAD];   // Q lo
__device__ __half g_kh[(size_t)BH * S_LEN * DHEAD];   // K hi
__device__ __half g_kl[(size_t)BH * S_LEN * DHEAD];   // K lo
__device__ __half g_vth[(size_t)BH * DHEAD * S_LEN];  // V^T hi [bh][d][s]

__device__ __forceinline__ void h_split(float v, __half& hi, __half& lo) {
    hi = __float2half_rn(v);
    lo = __float2half_rn(v - __half2float(hi));
}

// ---------------------------------------------------------------------------
// Convert x [4096][1024] f32 -> g_xh fp16
// ---------------------------------------------------------------------------
__global__ __launch_bounds__(256) void conv_x_kernel(const float* __restrict__ src)
{
    int idx = blockIdx.x * 256 + threadIdx.x;
    int m = idx >> 8;
    int c = (idx & 255) << 2;
    float4 v = *(const float4*)(src + (size_t)m * KD + c);
    size_t o = (size_t)m * KD + c;
    *(__half2*)(g_xh + o)     = __half2{__float2half_rn(v.x), __float2half_rn(v.y)};
    *(__half2*)(g_xh + o + 2) = __half2{__float2half_rn(v.z), __float2half_rn(v.w)};
}

// ---------------------------------------------------------------------------
// Transpose + fp16 convert BOTH weights in one launch.
// ---------------------------------------------------------------------------
__global__ __launch_bounds__(256) void wconv_all_kernel(
    const float* __restrict__ Wq, const float* __restrict__ Wo)
{
    __shared__ float tile[32][33];
    const int bx = blockIdx.x;
    const float* src; __half* dst; int NC, n0;
    if (bx < 96) { src = Wq; dst = g_wqh; NC = 3072; n0 = bx * 32; }
    else         { src = Wo; dst = g_woh; NC = 1024; n0 = (bx - 96) * 32; }
    int k0 = blockIdx.y * 32;
    int tx = threadIdx.x, ty = threadIdx.y;   // 32 x 8
#pragma unroll
    for (int i = 0; i < 32; i += 8)
        tile[ty + i][tx] = src[(size_t)(k0 + ty + i) * NC + n0 + tx];
    __syncthreads();
#pragma unroll
    for (int i = 0; i < 32; i += 8) {
        float v = tile[tx][ty + i];
        int n = n0 + ty + i, k = k0 + tx;
        dst[(size_t)n * KD + k] = __float2half_rn(v);
    }
}

// ---------------------------------------------------------------------------
// fp16 mma.sync GEMM (R12-validated config).
// MODE 0: Q pre-scaled by SCALE_L2E before hi/lo split; K hi/lo; V^T scatter.
// MODE 1: A=g_ch B=g_woh -> fp32 out.
// ---------------------------------------------------------------------------
#define BM 128
#define BN 128
#define BK 32
#define NIT 32
#define SB_OFF 8192
#define STG_BYTES 16384
#define SMEM_DYN (4 * STG_BYTES)

template <int MODE>
__global__ __launch_bounds__(256, 2) void mma_gemm_kernel(
    const float* __restrict__ bias, float* __restrict__ out)
{
    extern __shared__ char dsm[];
    const __half* __restrict__ Ah = MODE ? g_ch : g_xh;
    const __half* __restrict__ Bh = MODE ? g_woh : g_wqh;

    const int tid = threadIdx.x;
    const int wid = tid >> 5, lid = tid & 31;
    const int m0 = blockIdx.y * BM, n0 = blockIdx.x * BN;
    const int wm = wid & 3, wn = wid >> 2;
    const uint32_t sbase = smem_u32(dsm);

    const int row = tid >> 1;
    const int c0  = (tid & 1) << 1;
    const int sw  = (row >> 1) & 3;
    const __half* gA = Ah + (size_t)(m0 + row) * KD;
    const __half* gB = Bh + (size_t)(n0 + row) * KD;
    uint32_t dA[2], dB[2];
#pragma unroll
    for (int j = 0; j < 2; j++) {
        dA[j] = sbase + (uint32_t)(row * 64 + (((c0 + j) ^ sw) << 4));
        dB[j] = dA[j] + SB_OFF;
    }

    uint32_t aAd[2], bAd[4];
#pragma unroll
    for (int mi = 0; mi < 2; mi++) {
        int r = wm * 32 + mi * 16 + (lid & 15);
        int e0 = (lid >> 4) ^ ((r >> 1) & 3);
        aAd[mi] = sbase + (uint32_t)(r * 64 + (e0 << 4));
    }
#pragma unroll
    for (int ni = 0; ni < 4; ni++) {
        int r = wn * 64 + ni * 16 + ((lid >> 4) << 3) + (lid & 7);
        int e0 = ((lid >> 3) & 1) ^ ((r >> 1) & 3);
        bAd[ni] = sbase + SB_OFF + (uint32_t)(r * 64 + (e0 << 4));
    }

    float acc[2][8][4];
#pragma unroll
    for (int i = 0; i < 2; i++)
#pragma unroll
        for (int j = 0; j < 8; j++)
#pragma unroll
            for (int k = 0; k < 4; k++) acc[i][j][k] = 0.f;

#pragma unroll
    for (int s = 0; s < 3; s++) {
        const int k0 = s * BK;
        const uint32_t so = s * STG_BYTES;
        cpa16(dA[0] + so, gA + k0 + c0 * 8);
        cpa16(dA[1] + so, gA + k0 + (c0 + 1) * 8);
        cpa16(dB[0] + so, gB + k0 + c0 * 8);
        cpa16(dB[1] + so, gB + k0 + (c0 + 1) * 8);
        CP_COMMIT();
    }

    for (int kt = 0; kt < NIT; ++kt) {
        CP_WAIT2();
        __syncthreads();
        if (kt + 3 < NIT) {
            const int k0 = (kt + 3) * BK;
            const uint32_t so = ((kt + 3) & 3) * STG_BYTES;
            cpa16(dA[0] + so, gA + k0 + c0 * 8);
            cpa16(dA[1] + so, gA + k0 + (c0 + 1) * 8);
            cpa16(dB[0] + so, gB + k0 + c0 * 8);
            cpa16(dB[1] + so, gB + k0 + (c0 + 1) * 8);
        }
        CP_COMMIT();

        const uint32_t so = (kt & 3) * STG_BYTES;
        uint32_t ar0[2][4], br0[4][4], ar1[2][4], br1[4][4];
        ldsm4(ar0[0], aAd[0] + so);
        ldsm4(ar0[1], aAd[1] + so);
#pragma unroll
        for (int ni = 0; ni < 4; ni++) ldsm4(br0[ni], bAd[ni] + so);
        ldsm4(ar1[0], (aAd[0] + so) ^ 32u);
        ldsm4(ar1[1], (aAd[1] + so) ^ 32u);
#pragma unroll
        for (int mi = 0; mi < 2; mi++)
#pragma unroll
            for (int n8 = 0; n8 < 8; n8++)
                mma16816(acc[mi][n8], ar0[mi], &br0[n8 >> 1][(n8 & 1) << 1]);
#pragma unroll
        for (int ni = 0; ni < 4; ni++) ldsm4(br1[ni], (bAd[ni] + so) ^ 32u);
#pragma unroll
        for (int mi = 0; mi < 2; mi++)
#pragma unroll
            for (int n8 = 0; n8 < 8; n8++)
                mma16816(acc[mi][n8], ar1[mi], &br1[n8 >> 1][(n8 & 1) << 1]);
    }

    // ---- epilogue
    const int row_l = lid >> 2;
    const int col_l = (lid & 3) << 1;
#pragma unroll
    for (int ni = 0; ni < 8; ni++) {
        const int c = n0 + wn * 64 + ni * 8 + col_l;
        const float bx = bias[c], by = bias[c + 1];
#pragma unroll
        for (int mi = 0; mi < 2; mi++) {
            const int r = m0 + wm * 32 + mi * 16 + row_l;
            float x00 = acc[mi][ni][0] + bx, x01 = acc[mi][ni][1] + by;
            float x10 = acc[mi][ni][2] + bx, x11 = acc[mi][ni][3] + by;
            if (MODE == 0) {
                const int part = c >> 10;
                const int hh   = (c & 1023) >> 6;
                const int d    = c & 63;
                const int bb   = r >> 11;
                const int s    = r & 2047;
                const int bhi  = bb * NHEADS + hh;
                if (part < 2) {
                    if (part == 0) {     // fold ATT_SCALE*log2(e) into Q
                        x00 *= SCALE_L2E; x01 *= SCALE_L2E;
                        x10 *= SCALE_L2E; x11 *= SCALE_L2E;
                    }
                    __half h00, h01, h10, h11, l00, l01, l10, l11;
                    h_split(x00, h00, l00); h_split(x01, h01, l01);
                    h_split(x10, h10, l10); h_split(x11, h11, l11);
                    __half* dh = (part == 0 ? g_qh : g_kh) + ((size_t)bhi * S_LEN + s) * DHEAD + d;
                    __half* dl = (part == 0 ? g_ql : g_kl) + ((size_t)bhi * S_LEN + s) * DHEAD + d;
                    *(__half2*)dh                 = __half2{h00, h01};
                    *(__half2*)(dh + 8 * DHEAD)   = __half2{h10, h11};
                    *(__half2*)dl                 = __half2{l00, l01};
                    *(__half2*)(dl + 8 * DHEAD)   = __half2{l10, l11};
                } else {
                    __half* th = g_vth + ((size_t)bhi * DHEAD + d) * S_LEN + s;
                    th[0] = __float2half_rn(x00); th[S_LEN]     = __float2half_rn(x01);
                    th[8] = __float2half_rn(x10); th[S_LEN + 8] = __float2half_rn(x11);
                }
            } else {
                float* p = out + (size_t)r * DMODEL + c;
                *(float2*)p                = make_float2(x00, x01);
                *(float2*)(p + 8 * DMODEL) = make_float2(x10, x11);
            }
        }
    }
}

// ---------------------------------------------------------------------------
// Tensor-core flash attention. QK 3-term (base-2 logits, scale pre-folded),
// PV 1-term. Full-window tiles skip masking entirely; exp via exp2f.
// ---------------------------------------------------------------------------
#define OFF_QL 8192
#define OFF_K  16384
#define OFF_VT 32768

__global__ __launch_bounds__(128, 3) void attn_kernel()
{
    __shared__ __align__(1024) char smbuf[40960];
    const uint32_t sb = smem_u32(smbuf);
    const int tid = threadIdx.x;
    const int lid = tid & 31, wid = tid >> 5;
    const int q0 = blockIdx.x * 64;
    const int bh = blockIdx.y;
    const int hh = bh & 15, bb = bh >> 4;
    const int nT = min(10, (S_LEN - q0) >> 5);

    const __half* Qhp = g_qh + (size_t)bh * S_LEN * DHEAD;
    const __half* Qlp = g_ql + (size_t)bh * S_LEN * DHEAD;
    const __half* Khp = g_kh + (size_t)bh * S_LEN * DHEAD;
    const __half* Klp = g_kl + (size_t)bh * S_LEN * DHEAD;
    const __half* Vhp = g_vth + (size_t)bh * DHEAD * S_LEN;

    {
        int r = tid >> 1, j0 = (tid & 1) * 4;
        const __half* sh = Qhp + (size_t)(q0 + r) * DHEAD;
        const __half* sl = Qlp + (size_t)(q0 + r) * DHEAD;
        uint32_t rb = sb + r * 128;
#pragma unroll
        for (int j = j0; j < j0 + 4; j++) {
            uint32_t o = (uint32_t)((j ^ (r & 7)) << 4);
            cpa16(rb + o, sh + j * 8);
            cpa16(rb + OFF_QL + o, sl + j * 8);
        }
    }
    CP_COMMIT();

    auto load_tile = [&](int t) {
        int kt0 = q0 + t * 32, s = t & 1;
        {
            int r = tid >> 2, j0 = (tid & 3) * 2;
            const __half* sh = Khp + (size_t)(kt0 + r) * DHEAD;
            const __half* sl = Klp + (size_t)(kt0 + r) * DHEAD;
            uint32_t kb = sb + OFF_K + s * 8192 + r * 128;
#pragma unroll
            for (int j = j0; j < j0 + 2; j++) {
                uint32_t o = (uint32_t)((j ^ (r & 7)) << 4);
                cpa16(kb + o, sh + j * 8);
                cpa16(kb + 4096 + o, sl + j * 8);
            }
        }
        {
            int r = tid >> 1;
            int jj0 = (tid & 1) * 2;
            const __half* sh = Vhp + (size_t)r * S_LEN + kt0;
            uint32_t vb = sb + OFF_VT + s * 4096 + r * 64;
#pragma unroll
            for (int jc = jj0; jc < jj0 + 2; jc++) {
                uint32_t o = (uint32_t)((jc ^ ((r >> 1) & 3)) << 4);
                cpa16(vb + o, sh + jc * 8);
            }
        }
    };
    load_tile(0); CP_COMMIT();
    load_tile(1); CP_COMMIT();
    CP_WAIT1();
    __syncthreads();

    uint32_t qh[4][4], ql[4][4];
    {
        int r = wid * 16 + (lid & 15);
        uint32_t base = (uint32_t)(r * 128 + (((lid >> 4) ^ (r & 7)) << 4));
#pragma unroll
        for (int kc = 0; kc < 4; kc++) {
            ldsm4(qh[kc], (sb + base) ^ (uint32_t)(kc << 5));
            ldsm4(ql[kc], (sb + OFF_QL + base) ^ (uint32_t)(kc << 5));
        }
    }

    uint32_t kadr[2], vadr[4];
#pragma unroll
    for (int ni = 0; ni < 2; ni++) {
        int r = ni * 16 + ((lid >> 4) << 3) + (lid & 7);
        kadr[ni] = (uint32_t)(r * 128 + ((((lid >> 3) & 1) ^ (r & 7)) << 4));
    }
#pragma unroll
    for (int ni = 0; ni < 4; ni++) {
        int r = ni * 16 + ((lid >> 4) << 3) + (lid & 7);
        vadr[ni] = (uint32_t)(r * 64 + ((((lid >> 3) & 1) ^ ((r >> 1) & 3)) << 4));
    }

    float od[8][4];
#pragma unroll
    for (int i = 0; i < 8; i++) { od[i][0] = od[i][1] = od[i][2] = od[i][3] = 0.f; }
    float m0 = -1e30f, m1 = -1e30f, l0 = 0.f, l1 = 0.f;
    const int qr0 = q0 + wid * 16 + (lid >> 2);
    const int qr1 = qr0 + 8;
    const int kcol = (lid & 3) << 1;
    const int wlo = q0 + wid * 16;

    for (int t = 0; t < nT; ++t) {
        const int kt0 = q0 + t * 32, s = t & 1;
        const bool active = (kt0 + 31 >= wlo) && (kt0 <= wlo + 15 + WIN - 1);
        if (active) {
            float sc[4][4];
#pragma unroll
            for (int i = 0; i < 4; i++) { sc[i][0] = sc[i][1] = sc[i][2] = sc[i][3] = 0.f; }
            const uint32_t kbh = sb + OFF_K + s * 8192;
            const uint32_t kbl = kbh + 4096;
#pragma unroll
            for (int kc = 0; kc < 4; kc++) {
                const uint32_t kx = (uint32_t)(kc << 5);
                uint32_t kh2[2][4], kl2[2][4];
                ldsm4(kh2[0], (kbh + kadr[0]) ^ kx);
                ldsm4(kh2[1], (kbh + kadr[1]) ^ kx);
                ldsm4(kl2[0], (kbl + kadr[0]) ^ kx);
                ldsm4(kl2[1], (kbl + kadr[1]) ^ kx);
#pragma unroll
                for (int ni = 0; ni < 2; ni++)
#pragma unroll
                    for (int hf = 0; hf < 2; hf++) {
                        int n8 = ni * 2 + hf;
                        mma16816(sc[n8], qh[kc], &kh2[ni][hf * 2]);
                        mma16816(sc[n8], ql[kc], &kh2[ni][hf * 2]);
                        mma16816(sc[n8], qh[kc], &kl2[ni][hf * 2]);
                    }
            }
            // ---- mask only boundary tiles (scores already scaled, base-2)
            const bool full = (kt0 >= wlo + 15) && (kt0 + 31 <= wlo + WIN - 1);
            if (!full) {
#pragma unroll
                for (int n8 = 0; n8 < 4; n8++) {
#pragma unroll
                    for (int jj = 0; jj < 2; jj++) {
                        int key = kt0 + n8 * 8 + kcol + jj;
                        if (!(key >= qr0 && key < qr0 + WIN)) sc[n8][jj]     = -INFINITY;
                        if (!(key >= qr1 && key < qr1 + WIN)) sc[n8][2 + jj] = -INFINITY;
                    }
                }
            }
            float t0 = fmaxf(fmaxf(sc[0][0], sc[0][1]), fmaxf(sc[1][0], sc[1][1]));
            t0 = fmaxf(t0, fmaxf(fmaxf(sc[2][0], sc[2][1]), fmaxf(sc[3][0], sc[3][1])));
            float t1 = fmaxf(fmaxf(sc[0][2], sc[0][3]), fmaxf(sc[1][2], sc[1][3]));
            t1 = fmaxf(t1, fmaxf(fmaxf(sc[2][2], sc[2][3]), fmaxf(sc[3][2], sc[3][3])));
            t0 = fmaxf(t0, __shfl_xor_sync(0xffffffffu, t0, 1));
            t0 = fmaxf(t0, __shfl_xor_sync(0xffffffffu, t0, 2));
            t1 = fmaxf(t1, __shfl_xor_sync(0xffffffffu, t1, 1));
            t1 = fmaxf(t1, __shfl_xor_sync(0xffffffffu, t1, 2));
            float nm0 = fmaxf(m0, t0), nm1 = fmaxf(m1, t1);
            float f0 = exp2f(m0 - nm0), f1 = exp2f(m1 - nm1);
            m0 = nm0; m1 = nm1;
            float s0 = 0.f, s1 = 0.f;
#pragma unroll
            for (int n8 = 0; n8 < 4; n8++) {
                sc[n8][0] = exp2f(sc[n8][0] - nm0); s0 += sc[n8][0];
                sc[n8][1] = exp2f(sc[n8][1] - nm0); s0 += sc[n8][1];
                sc[n8][2] = exp2f(sc[n8][2] - nm1); s1 += sc[n8][2];
                sc[n8][3] = exp2f(sc[n8][3] - nm1); s1 += sc[n8][3];
            }
            s0 += __shfl_xor_sync(0xffffffffu, s0, 1);
            s0 += __shfl_xor_sync(0xffffffffu, s0, 2);
            s1 += __shfl_xor_sync(0xffffffffu, s1, 1);
            s1 += __shfl_xor_sync(0xffffffffu, s1, 2);
            l0 = l0 * f0 + s0; l1 = l1 * f1 + s1;
#pragma unroll
            for (int n8 = 0; n8 < 8; n8++) {
                od[n8][0] *= f0; od[n8][1] *= f0;
                od[n8][2] *= f1; od[n8][3] *= f1;
            }
            uint32_t ph[2][4];
#pragma unroll
            for (int kp = 0; kp < 2; kp++)
#pragma unroll
                for (int rg = 0; rg < 4; rg++) {
                    int n8 = kp * 2 + (rg >> 1);
                    float pa = sc[n8][(rg & 1) * 2 + 0];
                    float pb = sc[n8][(rg & 1) * 2 + 1];
                    __half ha = __float2half_rn(pa), hb = __float2half_rn(pb);
                    ph[kp][rg] = ((uint32_t)__half_as_ushort(hb) << 16) | __half_as_ushort(ha);
                }
            const uint32_t vbh = sb + OFF_VT + s * 4096;
#pragma unroll
            for (int kp = 0; kp < 2; kp++) {
                const uint32_t kx = (uint32_t)(kp << 5);
                uint32_t vh2[4][4];
#pragma unroll
                for (int ni = 0; ni < 4; ni++)
                    ldsm4(vh2[ni], (vbh + vadr[ni]) ^ kx);
#pragma unroll
                for (int ni = 0; ni < 4; ni++)
#pragma unroll
                    for (int hf = 0; hf < 2; hf++) {
                        int n8 = ni * 2 + hf;
                        mma16816(od[n8], ph[kp], &vh2[ni][hf * 2]);
                    }
            }
        }
        __syncthreads();
        if (t + 1 < nT) {
            if (t + 2 < nT) { load_tile(t + 2); CP_COMMIT(); CP_WAIT1(); }
            else            { CP_WAIT0(); }
            __syncthreads();
        }
    }

    const float inv0 = 1.0f / l0, inv1 = 1.0f / l1;
    const size_t o0 = ((size_t)(bb * S_LEN + qr0)) * KD + hh * 64;
    const size_t o1 = ((size_t)(bb * S_LEN + qr1)) * KD + hh * 64;
#pragma unroll
    for (int n8 = 0; n8 < 8; n8++) {
        int d = n8 * 8 + kcol;
        *(__half2*)(g_ch + o0 + d) =
            __half2{__float2half_rn(od[n8][0] * inv0), __float2half_rn(od[n8][1] * inv0)};
        *(__half2*)(g_ch + o1 + d) =
            __half2{__float2half_rn(od[n8][2] * inv1), __float2half_rn(od[n8][3] * inv1)};
    }
}

// ---------------------------------------------------------------------------
extern "C" void kernel_launch(void* const* d_in, const int* in_sizes, int n_in,
                              void* d_out, int out_size)
{
    const float* x    = (const float*)d_in[0];
    const float* Wqkv = (const float*)d_in[1];
    const float* bqkv = (const float*)d_in[2];
    const float* Wout = (const float*)d_in[3];
    const float* bout = (const float*)d_in[4];
    float* out = (float*)d_out;
    (void)in_sizes; (void)n_in; (void)out_size;

    cudaFuncSetAttribute(mma_gemm_kernel<0>, cudaFuncAttributeMaxDynamicSharedMemorySize, SMEM_DYN);
    cudaFuncSetAttribute(mma_gemm_kernel<1>, cudaFuncAttributeMaxDynamicSharedMemorySize, SMEM_DYN);

    conv_x_kernel<<<MROWS * KD / 4 / 256, 256>>>(x);
    wconv_all_kernel<<<dim3(128, DMODEL / 32), dim3(32, 8)>>>(Wqkv, Wout);

    // QKV projection: M=4096, N=3072, K=1024 (fp16 mma.sync, BK=32, 4 stages)
    mma_gemm_kernel<0><<<dim3(3 * DMODEL / BN, MROWS / BM), 256, SMEM_DYN>>>(bqkv, nullptr);
    // Tensor-core flash attention -> g_ch
    attn_kernel<<<dim3(S_LEN / 64, BH), 128>>>();
    // Output projection: M=4096, N=1024, K=1024
    mma_gemm_kernel<1><<<dim3(DMODEL / BN, MROWS / BM), 256, SMEM_DYN>>>(bout, out);
}